// round 7
// baseline (speedup 1.0000x reference)
#include <cuda_runtime.h>
#include <math.h>
#include <stdint.h>

// ---------------------------------------------------------------------------
// EGNN  B=4, N=10000, E=160000, D=128, OUT=64, L=4
// R6: tf32 3-pass tensor-core GEMMs with PRE-SPLIT (hi,lo) packed SMEM tiles;
//     mainloop = LDS.64 + HMMA only. 512 threads, 16 warps, warp tile 32x32.
// ---------------------------------------------------------------------------
#define BATCH    4
#define NNODES   10000
#define NEDGES   160000
#define DIM      128
#define OUTD     64
#define NLAYERS  4
#define NEG      0.01f

#define TM       128
#define TN       128
#define BK       32
#define PAD      4
#define STR      (TM + PAD)     // 132, fp32 tile stride (Hs)
#define STRP     (TM + PAD)     // 132, packed (uint2) tile stride
#define NTHREADS 512
#define NPART    20

// ------------------------- device scratch (no mallocs) ---------------------
__device__ float g_pos[BATCH * NNODES * 3];
__device__ float g_h[(size_t)BATCH * NNODES * DIM];
__device__ float g_aggr[(size_t)BATCH * NNODES * DIM];
__device__ float g_msg[(size_t)BATCH * NEDGES * DIM];
__device__ int   g_cnt[NNODES];
__device__ float g_recip[NNODES];
__device__ int   g_off[NNODES + 1];
__device__ int   g_cursor[NNODES];
__device__ int   g_perm[NEDGES];
__device__ float g_hpart[BATCH * NPART * DIM];

__device__ __forceinline__ float lrelu(float x) { return x > 0.f ? x : NEG * x; }

// ---- tf32 split + mma helpers ---------------------------------------------
__device__ __forceinline__ uint2 split2(float x) {
    uint2 r;
    asm("cvt.rna.tf32.f32 %0, %1;" : "=r"(r.x) : "f"(x));
    float l = x - __uint_as_float(r.x);
    asm("cvt.rna.tf32.f32 %0, %1;" : "=r"(r.y) : "f"(l));
    return r;
}

__device__ __forceinline__ void mma8(float* c, const uint32_t* a, const uint32_t* b) {
    asm("mma.sync.aligned.m16n8k8.row.col.f32.tf32.tf32.f32 "
        "{%0,%1,%2,%3}, {%4,%5,%6,%7}, {%8,%9}, {%0,%1,%2,%3};"
        : "+f"(c[0]), "+f"(c[1]), "+f"(c[2]), "+f"(c[3])
        : "r"(a[0]), "r"(a[1]), "r"(a[2]), "r"(a[3]), "r"(b[0]), "r"(b[1]));
}

// 3-pass accumulate: hi*hi + hi*lo + lo*hi
__device__ __forceinline__ void mma3(float* c, const uint2* a2, const uint2* b2) {
    uint32_t ah[4] = {a2[0].x, a2[1].x, a2[2].x, a2[3].x};
    uint32_t al[4] = {a2[0].y, a2[1].y, a2[2].y, a2[3].y};
    uint32_t bh[2] = {b2[0].x, b2[1].x};
    uint32_t bl[2] = {b2[0].y, b2[1].y};
    mma8(c, ah, bh);
    mma8(c, ah, bl);
    mma8(c, al, bh);
}

// ------------------------------ CSR build ----------------------------------
__global__ void k_zero_cnt() {
    int n = blockIdx.x * blockDim.x + threadIdx.x;
    if (n < NNODES) g_cnt[n] = 0;
}

__global__ void k_count(const int* __restrict__ col) {
    int e = blockIdx.x * blockDim.x + threadIdx.x;
    if (e < NEDGES) atomicAdd(&g_cnt[col[e]], 1);
}

__global__ void k_scan() {
    __shared__ int ss[1024];
    int tid = threadIdx.x;
    int running = 0;
    for (int c = 0; c < 10; ++c) {
        int n = c * 1024 + tid;
        int v = (n < NNODES) ? g_cnt[n] : 0;
        ss[tid] = v;
        __syncthreads();
        for (int d = 1; d < 1024; d <<= 1) {
            int t = (tid >= d) ? ss[tid - d] : 0;
            __syncthreads();
            ss[tid] += t;
            __syncthreads();
        }
        int incl = ss[tid];
        if (n < NNODES) {
            g_off[n + 1]  = running + incl;
            g_cursor[n]   = running + incl - v;
            g_recip[n]    = 1.0f / fmaxf((float)v, 1.0f);
        }
        if (c == 0 && tid == 0) g_off[0] = 0;
        int tot = ss[1023];
        __syncthreads();
        running += tot;
    }
}

__global__ void k_fill(const int* __restrict__ col) {
    int e = blockIdx.x * blockDim.x + threadIdx.x;
    if (e < NEDGES) {
        int p = atomicAdd(&g_cursor[col[e]], 1);
        g_perm[p] = e;
    }
}

__global__ void k_sort() {
    int n = blockIdx.x * blockDim.x + threadIdx.x;
    if (n >= NNODES) return;
    int s = g_off[n], t = g_off[n + 1];
    for (int i = s + 1; i < t; ++i) {
        int v = g_perm[i];
        int j = i - 1;
        while (j >= s && g_perm[j] > v) { g_perm[j + 1] = g_perm[j]; --j; }
        g_perm[j + 1] = v;
    }
}

// ------------------------------ init ---------------------------------------
__global__ void k_init_pos(const float* __restrict__ x) {
    int i = blockIdx.x * blockDim.x + threadIdx.x;
    if (i < BATCH * NNODES * 3) g_pos[i] = x[i];
}

__global__ void k_h0(const float* __restrict__ w0, const float* __restrict__ b0) {
    int i = blockIdx.x * blockDim.x + threadIdx.x;
    if (i >= BATCH * NNODES * DIM) return;
    int j  = i & (DIM - 1);
    int bn = i >> 7;
    const float* p = &g_pos[bn * 3];
    float v = b0[j] + p[0] * w0[j] + p[1] * w0[DIM + j] + p[2] * w0[2 * DIM + j];
    g_h[i] = lrelu(v);
}

// --------------------- fused 2-layer MLP GEMM kernel ------------------------
// CTA 128x128, 512 threads (16 warps), warp tile 32x32.
// GEMM1: A,W pre-split to packed (hi,lo) uint2 SMEM tiles -> mainloop is
//        LDS.64 + HMMA only. GEMM2: A (hidden, fp32 SMEM) split on the fly,
//        W2 pre-split at chunk load.
template <bool EDGE>
__global__ void __launch_bounds__(NTHREADS)
mlp_kernel(const int* __restrict__ row, const int* __restrict__ col,
           const float* __restrict__ W1, const float* __restrict__ b1,
           const float* __restrict__ W2, const float* __restrict__ b2)
{
    extern __shared__ float smem[];
    uint2* As_p = (uint2*)smem;                 // [BK][STRP] packed A
    uint2* Ws_p = As_p + BK * STRP;             // [BK][STRP] packed W
    float* Hs   = (float*)(Ws_p + BK * STRP);   // [TN][STR]  hidden, feat-major
    float* dsq  = Hs + TN * STR;                // [TM]
    int*   nid  = (int*)(dsq + TM);             // [2*TM]

    const int b    = blockIdx.y;
    const int m0   = blockIdx.x * TM;
    const int tid  = threadIdx.x;
    const int wid  = tid >> 5;
    const int lane = tid & 31;
    const int gid  = lane >> 2;   // 0..7
    const int tig  = lane & 3;    // 0..3
    const int wm   = (wid & 3) * 32;    // 4 warps over M=128
    const int wn   = (wid >> 2) * 32;   // 4 warps over N=128

    const float* hb = g_h    + (size_t)b * NNODES * DIM;
    const float* ab = g_aggr + (size_t)b * NNODES * DIM;

    if (EDGE) {
        for (int i = tid; i < TM; i += NTHREADS) {
            int e = m0 + i;
            int r = row[e], c = col[e];
            nid[i]      = r;
            nid[TM + i] = c;
            const float* pr = &g_pos[((size_t)b * NNODES + r) * 3];
            const float* pc = &g_pos[((size_t)b * NNODES + c) * 3];
            float dx = pr[0] - pc[0], dy = pr[1] - pc[1], dz = pr[2] - pc[2];
            dsq[i] = dx * dx + dy * dy + dz * dz;
        }
        __syncthreads();
    }

    float acc[2][4][4];
#pragma unroll
    for (int mi = 0; mi < 2; ++mi)
#pragma unroll
        for (int ni = 0; ni < 4; ++ni)
#pragma unroll
            for (int c = 0; c < 4; ++c) acc[mi][ni][c] = 0.f;

    // ---------------- GEMM 1: K = 256 (8 chunks); +dsq column for EDGE ------
#pragma unroll 1
    for (int kc = 0; kc < 8; ++kc) {
        const int k0 = kc * BK;
        // gathered A tile -> split -> packed SMEM (k-major)
        for (int s = tid; s < TM * 8; s += NTHREADS) {
            int ei = s >> 3, q = s & 7;
            const float* src;
            if (EDGE) {
                int node = (kc < 4) ? nid[ei] : nid[TM + ei];
                int kh   = (kc < 4) ? k0 : (k0 - DIM);
                src = hb + (size_t)node * DIM + kh + q * 4;
            } else {
                int node = m0 + ei;
                if (node >= NNODES) node = NNODES - 1;
                src = (kc < 4) ? (hb + (size_t)node * DIM + k0 + q * 4)
                               : (ab + (size_t)node * DIM + (k0 - DIM) + q * 4);
            }
            float4 v = *(const float4*)src;
            uint2* dst = &As_p[(q * 4) * STRP + ei];
            dst[0]        = split2(v.x);
            dst[STRP]     = split2(v.y);
            dst[2 * STRP] = split2(v.z);
            dst[3 * STRP] = split2(v.w);
        }
        // W1 chunk -> split -> packed SMEM
        for (int s = tid; s < BK * TN / 4; s += NTHREADS) {
            int r = s >> 5, c4 = s & 31;
            float4 v = ((const float4*)(W1 + (size_t)k0 * TN))[s];
            uint2* dst = &Ws_p[r * STRP + c4 * 4];
            dst[0] = split2(v.x); dst[1] = split2(v.y);
            dst[2] = split2(v.z); dst[3] = split2(v.w);
        }
        __syncthreads();
#pragma unroll
        for (int k8 = 0; k8 < 4; ++k8) {
            const int ks = k8 * 8;
            uint2 a2[2][4];
#pragma unroll
            for (int mi = 0; mi < 2; ++mi)
#pragma unroll
                for (int r = 0; r < 4; ++r)
                    a2[mi][r] = As_p[(ks + tig + ((r >> 1) << 2)) * STRP
                                     + wm + mi * 16 + gid + ((r & 1) << 3)];
            uint2 b2f[4][2];
#pragma unroll
            for (int ni = 0; ni < 4; ++ni) {
                int nn = wn + ni * 8 + gid;
                b2f[ni][0] = Ws_p[(ks + tig) * STRP + nn];
                b2f[ni][1] = Ws_p[(ks + tig + 4) * STRP + nn];
            }
#pragma unroll
            for (int mi = 0; mi < 2; ++mi)
#pragma unroll
                for (int ni = 0; ni < 4; ++ni)
                    mma3(acc[mi][ni], a2[mi], b2f[ni]);
        }
        __syncthreads();
    }

    // epilogue 1: (+ dsq * W1[256]) + b1, lrelu, store hidden feature-major
    {
        float bb0[4], bb1[4], wl0[4], wl1[4];
#pragma unroll
        for (int ni = 0; ni < 4; ++ni) {
            int n0 = wn + ni * 8 + tig * 2;
            bb0[ni] = b1[n0];
            bb1[ni] = b1[n0 + 1];
            if (EDGE) { wl0[ni] = W1[256 * TN + n0]; wl1[ni] = W1[256 * TN + n0 + 1]; }
        }
        float dA[2] = {0.f, 0.f}, dB[2] = {0.f, 0.f};
        if (EDGE) {
#pragma unroll
            for (int mi = 0; mi < 2; ++mi) {
                dA[mi] = dsq[wm + mi * 16 + gid];
                dB[mi] = dsq[wm + mi * 16 + gid + 8];
            }
        }
#pragma unroll
        for (int mi = 0; mi < 2; ++mi) {
            int mA = wm + mi * 16 + gid, mB = mA + 8;
#pragma unroll
            for (int ni = 0; ni < 4; ++ni) {
                int n0 = wn + ni * 8 + tig * 2;
                float v0 = acc[mi][ni][0] + bb0[ni];
                float v1 = acc[mi][ni][1] + bb1[ni];
                float v2 = acc[mi][ni][2] + bb0[ni];
                float v3 = acc[mi][ni][3] + bb1[ni];
                if (EDGE) {
                    v0 = fmaf(dA[mi], wl0[ni], v0); v1 = fmaf(dA[mi], wl1[ni], v1);
                    v2 = fmaf(dB[mi], wl0[ni], v2); v3 = fmaf(dB[mi], wl1[ni], v3);
                }
                Hs[n0 * STR + mA]       = lrelu(v0);
                Hs[(n0 + 1) * STR + mA] = lrelu(v1);
                Hs[n0 * STR + mB]       = lrelu(v2);
                Hs[(n0 + 1) * STR + mB] = lrelu(v3);
            }
        }
    }
    __syncthreads();

    // ---------------- GEMM 2: K = 128 (4 chunks), W2 pre-split --------------
#pragma unroll
    for (int mi = 0; mi < 2; ++mi)
#pragma unroll
        for (int ni = 0; ni < 4; ++ni)
#pragma unroll
            for (int c = 0; c < 4; ++c) acc[mi][ni][c] = 0.f;

#pragma unroll 1
    for (int kc = 0; kc < 4; ++kc) {
        const int k0 = kc * BK;
        for (int s = tid; s < BK * TN / 4; s += NTHREADS) {
            int r = s >> 5, c4 = s & 31;
            float4 v = ((const float4*)(W2 + (size_t)k0 * TN))[s];
            uint2* dst = &Ws_p[r * STRP + c4 * 4];
            dst[0] = split2(v.x); dst[1] = split2(v.y);
            dst[2] = split2(v.z); dst[3] = split2(v.w);
        }
        __syncthreads();
        const float* Asrc = Hs + k0 * STR;
#pragma unroll
        for (int k8 = 0; k8 < 4; ++k8) {
            const int ks = k8 * 8;
            uint2 a2[2][4];
#pragma unroll
            for (int mi = 0; mi < 2; ++mi)
#pragma unroll
                for (int r = 0; r < 4; ++r)
                    a2[mi][r] = split2(Asrc[(ks + tig + ((r >> 1) << 2)) * STR
                                            + wm + mi * 16 + gid + ((r & 1) << 3)]);
            uint2 b2f[4][2];
#pragma unroll
            for (int ni = 0; ni < 4; ++ni) {
                int nn = wn + ni * 8 + gid;
                b2f[ni][0] = Ws_p[(ks + tig) * STRP + nn];
                b2f[ni][1] = Ws_p[(ks + tig + 4) * STRP + nn];
            }
#pragma unroll
            for (int mi = 0; mi < 2; ++mi)
#pragma unroll
                for (int ni = 0; ni < 4; ++ni)
                    mma3(acc[mi][ni], a2[mi], b2f[ni]);
        }
        __syncthreads();
    }

    // epilogue 2
    {
        float bb0[4], bb1[4];
#pragma unroll
        for (int ni = 0; ni < 4; ++ni) {
            int n0 = wn + ni * 8 + tig * 2;
            bb0[ni] = b2[n0];
            bb1[ni] = b2[n0 + 1];
        }
        if (EDGE) {
            float* mout = g_msg + ((size_t)b * NEDGES + m0) * DIM;
#pragma unroll
            for (int mi = 0; mi < 2; ++mi) {
                int mA = wm + mi * 16 + gid, mB = mA + 8;
#pragma unroll
                for (int ni = 0; ni < 4; ++ni) {
                    int n0 = wn + ni * 8 + tig * 2;
                    float2 vA = make_float2(lrelu(acc[mi][ni][0] + bb0[ni]),
                                            lrelu(acc[mi][ni][1] + bb1[ni]));
                    float2 vB = make_float2(lrelu(acc[mi][ni][2] + bb0[ni]),
                                            lrelu(acc[mi][ni][3] + bb1[ni]));
                    *(float2*)(mout + (size_t)mA * DIM + n0) = vA;
                    *(float2*)(mout + (size_t)mB * DIM + n0) = vB;
                }
            }
        } else {
            float* hout = g_h + (size_t)b * NNODES * DIM;
#pragma unroll
            for (int mi = 0; mi < 2; ++mi) {
                int mA = wm + mi * 16 + gid, mB = mA + 8;
                int nA = m0 + mA, nB = m0 + mB;
#pragma unroll
                for (int ni = 0; ni < 4; ++ni) {
                    int n0 = wn + ni * 8 + tig * 2;
                    if (nA < NNODES) {
                        float2* p = (float2*)(hout + (size_t)nA * DIM + n0);
                        float2 o = *p;
                        o.x += lrelu(acc[mi][ni][0] + bb0[ni]);
                        o.y += lrelu(acc[mi][ni][1] + bb1[ni]);
                        *p = o;
                    }
                    if (nB < NNODES) {
                        float2* p = (float2*)(hout + (size_t)nB * DIM + n0);
                        float2 o = *p;
                        o.x += lrelu(acc[mi][ni][2] + bb0[ni]);
                        o.y += lrelu(acc[mi][ni][3] + bb1[ni]);
                        *p = o;
                    }
                }
            }
        }
    }
}

// -------------------- CSR gather-mean aggregation ---------------------------
__global__ void k_aggr() {
    int b = blockIdx.y;
    int n = blockIdx.x * 2 + (threadIdx.x >> 7);
    int j = threadIdx.x & 127;
    const float* mb = g_msg + (size_t)b * NEDGES * DIM;
    int s = g_off[n], t = g_off[n + 1];
    float sum = 0.f;
    for (int i = s; i < t; ++i)
        sum += mb[(size_t)g_perm[i] * DIM + j];
    g_aggr[((size_t)b * NNODES + n) * DIM + j] = sum * g_recip[n];
}

// ----------------------- coord update (tanh GEMV) ---------------------------
__global__ void k_coord(const float* __restrict__ cw, const float* __restrict__ cb) {
    int b    = blockIdx.y;
    int wid  = threadIdx.x >> 5;
    int lane = threadIdx.x & 31;
    int n    = blockIdx.x * 8 + wid;
    if (n >= NNODES) return;
    const float* ar = g_aggr + ((size_t)b * NNODES + n) * DIM;
    float4 a = *(const float4*)(ar + lane * 4);
    float4 w = *(const float4*)(cw + lane * 4);
    float s = a.x * w.x + a.y * w.y + a.z * w.z + a.w * w.w;
#pragma unroll
    for (int o = 16; o; o >>= 1) s += __shfl_xor_sync(0xffffffffu, s, o);
    if (lane == 0) {
        float t = tanhf(s + cb[0]) * 0.1f;
        float* p = &g_pos[((size_t)b * NNODES + n) * 3];
        p[0] += t; p[1] += t; p[2] += t;
    }
}

// ----------------------- mean + projection ----------------------------------
__global__ void k_meanpart() {
    int b = blockIdx.y, p = blockIdx.x, j = threadIdx.x;   // 128 threads
    const float* hb = g_h + (size_t)b * NNODES * DIM;
    const int span = NNODES / NPART;                       // 500
    float s = 0.f;
    int n0 = p * span;
    for (int n = n0; n < n0 + span; ++n) s += hb[(size_t)n * DIM + j];
    g_hpart[(b * NPART + p) * DIM + j] = s;
}

__global__ void k_proj(const float* __restrict__ wp, const float* __restrict__ bp,
                       float* __restrict__ out) {
    __shared__ float hm[BATCH * DIM];
    int tid = threadIdx.x;  // 512
    {
        int b = tid >> 7, j = tid & 127;
        float s = 0.f;
        for (int p = 0; p < NPART; ++p) s += g_hpart[(b * NPART + p) * DIM + j];
        hm[b * DIM + j] = s * (1.0f / NNODES);
    }
    __syncthreads();
    if (tid < BATCH * OUTD) {
        int b = tid / OUTD, o = tid % OUTD;
        float s = bp[o];
        for (int j = 0; j < DIM; ++j) s = fmaf(hm[b * DIM + j], wp[j * OUTD + o], s);
        out[b * OUTD + o] = lrelu(s);
    }
}

// ---------------------------------------------------------------------------
extern "C" void kernel_launch(void* const* d_in, const int* in_sizes, int n_in,
                              void* d_out, int out_size) {
    const float* x   = (const float*)d_in[0];
    const int*   ei  = (const int*)  d_in[1];
    const float* w0  = (const float*)d_in[2];
    const float* b0  = (const float*)d_in[3];
    const float* ew1 = (const float*)d_in[4];
    const float* eb1 = (const float*)d_in[5];
    const float* ew2 = (const float*)d_in[6];
    const float* eb2 = (const float*)d_in[7];
    const float* cw  = (const float*)d_in[8];
    const float* cb  = (const float*)d_in[9];
    const float* nw1 = (const float*)d_in[10];
    const float* nb1 = (const float*)d_in[11];
    const float* nw2 = (const float*)d_in[12];
    const float* nb2 = (const float*)d_in[13];
    const float* wp  = (const float*)d_in[14];
    const float* bp  = (const float*)d_in[15];
    float* out = (float*)d_out;

    const int* row = ei;
    const int* col = ei + NEDGES;

    const int SMEM_MLP =
        2 * (BK * STRP * 8)                 // As_p + Ws_p (uint2)
        + TN * STR * 4 + TM * 4             // Hs + dsq
        + 2 * TM * 4;                       // nid   => 136,704 bytes

    cudaFuncSetAttribute(mlp_kernel<true>,
                         cudaFuncAttributeMaxDynamicSharedMemorySize, SMEM_MLP);
    cudaFuncSetAttribute(mlp_kernel<false>,
                         cudaFuncAttributeMaxDynamicSharedMemorySize, SMEM_MLP);

    // CSR build (deterministic after per-node sort)
    k_zero_cnt<<<(NNODES + 255) / 256, 256>>>();
    k_count<<<(NEDGES + 255) / 256, 256>>>(col);
    k_scan<<<1, 1024>>>();
    k_fill<<<(NEDGES + 255) / 256, 256>>>(col);
    k_sort<<<(NNODES + 127) / 128, 128>>>();

    // init
    k_init_pos<<<(BATCH * NNODES * 3 + 255) / 256, 256>>>(x);
    k_h0<<<(BATCH * NNODES * DIM + 255) / 256, 256>>>(w0, b0);

    for (int l = 0; l < NLAYERS; ++l) {
        mlp_kernel<true><<<dim3(NEDGES / TM, BATCH), NTHREADS, SMEM_MLP>>>(
            row, col,
            ew1 + (size_t)l * 257 * DIM, eb1 + l * DIM,
            ew2 + (size_t)l * DIM * DIM, eb2 + l * DIM);
        k_aggr<<<dim3(NNODES / 2, BATCH), 256>>>();
        k_coord<<<dim3(NNODES / 8, BATCH), 256>>>(cw + l * DIM, cb + l);
        mlp_kernel<false><<<dim3((NNODES + TM - 1) / TM, BATCH), NTHREADS, SMEM_MLP>>>(
            row, col,
            nw1 + (size_t)l * 2 * DIM * DIM, nb1 + l * DIM,
            nw2 + (size_t)l * DIM * DIM, nb2 + l * DIM);
    }

    k_meanpart<<<dim3(NPART, BATCH), 128>>>();
    k_proj<<<1, 512>>>(wp, bp, out);
}

// round 10
// speedup vs baseline: 1.0786x; 1.0786x over previous
#include <cuda_runtime.h>
#include <math.h>
#include <stdint.h>

// ---------------------------------------------------------------------------
// EGNN  B=4, N=10000, E=160000, D=128, OUT=64, L=4
// R9: R5 (mma.sync tf32 3-pass, 5431us) + weights pre-split ONCE per launch
//     into packed (hi,lo) global scratch -> B fragments become pure LDS.64,
//     no cvt/sub for B in the mainloop. A path unchanged from R5.
// ---------------------------------------------------------------------------
#define BATCH    4
#define NNODES   10000
#define NEDGES   160000
#define DIM      128
#define OUTD     64
#define NLAYERS  4
#define NEG      0.01f

#define TM       128
#define TN       128
#define BK       32
#define PAD      4
#define STR      (TM + PAD)   // 132
#define NTHREADS 256
#define NPART    20

// ------------------------- device scratch (no mallocs) ---------------------
__device__ float g_pos[BATCH * NNODES * 3];
__device__ float g_h[(size_t)BATCH * NNODES * DIM];
__device__ float g_aggr[(size_t)BATCH * NNODES * DIM];
__device__ float g_msg[(size_t)BATCH * NEDGES * DIM];
__device__ int   g_cnt[NNODES];
__device__ float g_recip[NNODES];
__device__ int   g_off[NNODES + 1];
__device__ int   g_cursor[NNODES];
__device__ int   g_perm[NEDGES];
__device__ float g_hpart[BATCH * NPART * DIM];
// pre-split weight chunks: 96 slots x [k=0..31][n=0..127] uint2{hi,lo}
__device__ uint2 g_wt[96 * 4096];

__device__ __forceinline__ float lrelu(float x) { return x > 0.f ? x : NEG * x; }

// ---- tf32 split + mma helpers ---------------------------------------------
__device__ __forceinline__ void split_tf32(float x, uint32_t& hi, uint32_t& lo) {
    asm("cvt.rna.tf32.f32 %0, %1;" : "=r"(hi) : "f"(x));
    float l = x - __uint_as_float(hi);
    asm("cvt.rna.tf32.f32 %0, %1;" : "=r"(lo) : "f"(l));
}
__device__ __forceinline__ uint2 split2(float x) {
    uint2 r;
    split_tf32(x, r.x, r.y);
    return r;
}

__device__ __forceinline__ void mma8(float* c, const uint32_t* a, const uint32_t* b) {
    asm("mma.sync.aligned.m16n8k8.row.col.f32.tf32.tf32.f32 "
        "{%0,%1,%2,%3}, {%4,%5,%6,%7}, {%8,%9}, {%0,%1,%2,%3};"
        : "+f"(c[0]), "+f"(c[1]), "+f"(c[2]), "+f"(c[3])
        : "r"(a[0]), "r"(a[1]), "r"(a[2]), "r"(a[3]), "r"(b[0]), "r"(b[1]));
}

// ------------------------------ CSR build ----------------------------------
__global__ void k_zero_cnt() {
    int n = blockIdx.x * blockDim.x + threadIdx.x;
    if (n < NNODES) g_cnt[n] = 0;
}
__global__ void k_count(const int* __restrict__ col) {
    int e = blockIdx.x * blockDim.x + threadIdx.x;
    if (e < NEDGES) atomicAdd(&g_cnt[col[e]], 1);
}
__global__ void k_scan() {
    __shared__ int ss[1024];
    int tid = threadIdx.x;
    int running = 0;
    for (int c = 0; c < 10; ++c) {
        int n = c * 1024 + tid;
        int v = (n < NNODES) ? g_cnt[n] : 0;
        ss[tid] = v;
        __syncthreads();
        for (int d = 1; d < 1024; d <<= 1) {
            int t = (tid >= d) ? ss[tid - d] : 0;
            __syncthreads();
            ss[tid] += t;
            __syncthreads();
        }
        int incl = ss[tid];
        if (n < NNODES) {
            g_off[n + 1] = running + incl;
            g_cursor[n]  = running + incl - v;
            g_recip[n]   = 1.0f / fmaxf((float)v, 1.0f);
        }
        if (c == 0 && tid == 0) g_off[0] = 0;
        int tot = ss[1023];
        __syncthreads();
        running += tot;
    }
}
__global__ void k_fill(const int* __restrict__ col) {
    int e = blockIdx.x * blockDim.x + threadIdx.x;
    if (e < NEDGES) {
        int p = atomicAdd(&g_cursor[col[e]], 1);
        g_perm[p] = e;
    }
}
__global__ void k_sort() {
    int n = blockIdx.x * blockDim.x + threadIdx.x;
    if (n >= NNODES) return;
    int s = g_off[n], t = g_off[n + 1];
    for (int i = s + 1; i < t; ++i) {
        int v = g_perm[i];
        int j = i - 1;
        while (j >= s && g_perm[j] > v) { g_perm[j + 1] = g_perm[j]; --j; }
        g_perm[j + 1] = v;
    }
}

// ------------------------------ init ---------------------------------------
__global__ void k_init_pos(const float* __restrict__ x) {
    int i = blockIdx.x * blockDim.x + threadIdx.x;
    if (i < BATCH * NNODES * 3) g_pos[i] = x[i];
}
__global__ void k_h0(const float* __restrict__ w0, const float* __restrict__ b0) {
    int i = blockIdx.x * blockDim.x + threadIdx.x;
    if (i >= BATCH * NNODES * DIM) return;
    int j  = i & (DIM - 1);
    int bn = i >> 7;
    const float* p = &g_pos[bn * 3];
    float v = b0[j] + p[0] * w0[j] + p[1] * w0[DIM + j] + p[2] * w0[2 * DIM + j];
    g_h[i] = lrelu(v);
}

// ---------------- weight prep: tf32-split every 32-row chunk ----------------
// slot = l*24 + c24.  c24: 0-7 ew1 (K=256), 8-11 ew2, 12-19 nw1, 20-23 nw2.
// g_wt[slot][k][n] = split(W[k0+k][n]).
__global__ void k_wprep(const float* __restrict__ ew1, const float* __restrict__ ew2,
                        const float* __restrict__ nw1, const float* __restrict__ nw2) {
    int slot = blockIdx.x;
    int l = slot / 24, c24 = slot % 24;
    const float* W; int k0;
    if (c24 < 8)       { W = ew1 + (size_t)l * 257 * DIM; k0 = c24 * 32; }
    else if (c24 < 12) { W = ew2 + (size_t)l * DIM * DIM; k0 = (c24 - 8) * 32; }
    else if (c24 < 20) { W = nw1 + (size_t)l * 2 * DIM * DIM; k0 = (c24 - 12) * 32; }
    else               { W = nw2 + (size_t)l * DIM * DIM; k0 = (c24 - 20) * 32; }
    uint2* dst = g_wt + (size_t)slot * 4096;
    for (int s = threadIdx.x; s < 4096; s += 256) {
        int k = s >> 7, n = s & 127;
        dst[s] = split2(W[(size_t)(k0 + k) * DIM + n]);
    }
}

// --------------------- fused 2-layer MLP GEMM kernel ------------------------
// Identical structure to R5 (CTA 128x128, 8 warps, warp tile 32x64),
// except W fragments come pre-split from g_wt as LDS.64.
template <bool EDGE>
__global__ void __launch_bounds__(NTHREADS)
mlp_kernel(const int* __restrict__ row, const int* __restrict__ col,
           int slot1, int slot2,
           const float* __restrict__ b1, const float* __restrict__ b2,
           const float* __restrict__ w1last)
{
    extern __shared__ float smem[];
    float* As   = smem;                        // [BK][STR] fp32 A chunk
    uint2* Ws_p = (uint2*)(As + BK * STR);     // [BK][STR] packed W chunk
    float* Hs   = (float*)(Ws_p + BK * STR);   // [TN][STR] hidden, feat-major
    float* dsq  = Hs + TN * STR;               // [TM]
    int*   nid  = (int*)(dsq + TM);            // [2*TM]

    const int b    = blockIdx.y;
    const int m0   = blockIdx.x * TM;
    const int tid  = threadIdx.x;
    const int wid  = tid >> 5;
    const int lane = tid & 31;
    const int gid  = lane >> 2;   // 0..7
    const int tig  = lane & 3;    // 0..3
    const int wm   = (wid & 3) * 32;    // 4 warps over M=128
    const int wn   = (wid >> 2) * 64;   // 2 warps over N=128

    const float* hb = g_h    + (size_t)b * NNODES * DIM;
    const float* ab = g_aggr + (size_t)b * NNODES * DIM;

    if (EDGE) {
        for (int i = tid; i < TM; i += NTHREADS) {
            int e = m0 + i;
            int r = row[e], c = col[e];
            nid[i]      = r;
            nid[TM + i] = c;
            const float* pr = &g_pos[((size_t)b * NNODES + r) * 3];
            const float* pc = &g_pos[((size_t)b * NNODES + c) * 3];
            float dx = pr[0] - pc[0], dy = pr[1] - pc[1], dz = pr[2] - pc[2];
            dsq[i] = dx * dx + dy * dy + dz * dz;
        }
        __syncthreads();
    }

    float acc[2][8][4];
#pragma unroll
    for (int mi = 0; mi < 2; ++mi)
#pragma unroll
        for (int ni = 0; ni < 8; ++ni)
#pragma unroll
            for (int c = 0; c < 4; ++c) acc[mi][ni][c] = 0.f;

    // ---------------- GEMM 1: K = 256 (8 chunks); +dsq column for EDGE ------
#pragma unroll 1
    for (int kc = 0; kc < 8; ++kc) {
        const int k0 = kc * BK;
        // gathered A tile (k-major in SMEM, fp32 — same as R5)
        for (int s = tid; s < TM * 8; s += NTHREADS) {
            int ei = s >> 3, q = s & 7;
            const float* src;
            if (EDGE) {
                int node = (kc < 4) ? nid[ei] : nid[TM + ei];
                int kh   = (kc < 4) ? k0 : (k0 - DIM);
                src = hb + (size_t)node * DIM + kh + q * 4;
            } else {
                int node = m0 + ei;
                if (node >= NNODES) node = NNODES - 1;
                src = (kc < 4) ? (hb + (size_t)node * DIM + k0 + q * 4)
                               : (ab + (size_t)node * DIM + (k0 - DIM) + q * 4);
            }
            float4 v = *(const float4*)src;
            float* dst = &As[(q * 4) * STR + ei];
            dst[0]       = v.x;
            dst[STR]     = v.y;
            dst[2 * STR] = v.z;
            dst[3 * STR] = v.w;
        }
        // pre-split W1 chunk: straight uint4 copy, padded rows in SMEM
        {
            const uint4* wsrc = (const uint4*)(g_wt + (size_t)(slot1 + kc) * 4096);
            for (int s = tid; s < 2048; s += NTHREADS) {
                int k = s >> 6, c = s & 63;          // 64 uint4 per k-row
                *(uint4*)&Ws_p[k * STR + c * 2] = wsrc[s];
            }
        }
        __syncthreads();
#pragma unroll
        for (int k8 = 0; k8 < 4; ++k8) {
            const int ks = k8 * 8;
            uint32_t ah[2][4], al[2][4];
#pragma unroll
            for (int mi = 0; mi < 2; ++mi)
#pragma unroll
                for (int r = 0; r < 4; ++r) {
                    int kk = ks + tig + ((r >> 1) << 2);
                    int mm = wm + mi * 16 + gid + ((r & 1) << 3);
                    split_tf32(As[kk * STR + mm], ah[mi][r], al[mi][r]);
                }
#pragma unroll
            for (int h = 0; h < 2; ++h) {
                uint32_t bh[4][2], bl[4][2];
#pragma unroll
                for (int ni = 0; ni < 4; ++ni) {
                    int nn = wn + (h * 4 + ni) * 8 + gid;
                    uint2 p0 = Ws_p[(ks + tig) * STR + nn];
                    uint2 p1 = Ws_p[(ks + tig + 4) * STR + nn];
                    bh[ni][0] = p0.x; bl[ni][0] = p0.y;
                    bh[ni][1] = p1.x; bl[ni][1] = p1.y;
                }
#pragma unroll
                for (int mi = 0; mi < 2; ++mi)
#pragma unroll
                    for (int ni = 0; ni < 4; ++ni) {
                        float* c = acc[mi][h * 4 + ni];
                        mma8(c, ah[mi], bh[ni]);
                        mma8(c, ah[mi], bl[ni]);
                        mma8(c, al[mi], bh[ni]);
                    }
            }
        }
        __syncthreads();
    }

    // epilogue 1: (+ dsq * W1[256]) + b1, lrelu, store hidden feature-major
    {
        float bb0[8], bb1[8], wl0[8], wl1[8];
#pragma unroll
        for (int ni = 0; ni < 8; ++ni) {
            int n0 = wn + ni * 8 + tig * 2;
            bb0[ni] = b1[n0];
            bb1[ni] = b1[n0 + 1];
            if (EDGE) { wl0[ni] = w1last[n0]; wl1[ni] = w1last[n0 + 1]; }
        }
        float dA[2] = {0.f, 0.f}, dB[2] = {0.f, 0.f};
        if (EDGE) {
#pragma unroll
            for (int mi = 0; mi < 2; ++mi) {
                dA[mi] = dsq[wm + mi * 16 + gid];
                dB[mi] = dsq[wm + mi * 16 + gid + 8];
            }
        }
#pragma unroll
        for (int mi = 0; mi < 2; ++mi) {
            int mA = wm + mi * 16 + gid, mB = mA + 8;
#pragma unroll
            for (int ni = 0; ni < 8; ++ni) {
                int n0 = wn + ni * 8 + tig * 2;
                float v0 = acc[mi][ni][0] + bb0[ni];
                float v1 = acc[mi][ni][1] + bb1[ni];
                float v2 = acc[mi][ni][2] + bb0[ni];
                float v3 = acc[mi][ni][3] + bb1[ni];
                if (EDGE) {
                    v0 = fmaf(dA[mi], wl0[ni], v0); v1 = fmaf(dA[mi], wl1[ni], v1);
                    v2 = fmaf(dB[mi], wl0[ni], v2); v3 = fmaf(dB[mi], wl1[ni], v3);
                }
                Hs[n0 * STR + mA]       = lrelu(v0);
                Hs[(n0 + 1) * STR + mA] = lrelu(v1);
                Hs[n0 * STR + mB]       = lrelu(v2);
                Hs[(n0 + 1) * STR + mB] = lrelu(v3);
            }
        }
    }
    __syncthreads();

    // ---------------- GEMM 2: K = 128 (4 chunks), W2 pre-split --------------
#pragma unroll
    for (int mi = 0; mi < 2; ++mi)
#pragma unroll
        for (int ni = 0; ni < 8; ++ni)
#pragma unroll
            for (int c = 0; c < 4; ++c) acc[mi][ni][c] = 0.f;

#pragma unroll 1
    for (int kc = 0; kc < 4; ++kc) {
        const int k0 = kc * BK;
        {
            const uint4* wsrc = (const uint4*)(g_wt + (size_t)(slot2 + kc) * 4096);
            for (int s = tid; s < 2048; s += NTHREADS) {
                int k = s >> 6, c = s & 63;
                *(uint4*)&Ws_p[k * STR + c * 2] = wsrc[s];
            }
        }
        __syncthreads();
        const float* Asrc = Hs + k0 * STR;
#pragma unroll
        for (int k8 = 0; k8 < 4; ++k8) {
            const int ks = k8 * 8;
            uint32_t ah[2][4], al[2][4];
#pragma unroll
            for (int mi = 0; mi < 2; ++mi)
#pragma unroll
                for (int r = 0; r < 4; ++r) {
                    int kk = ks + tig + ((r >> 1) << 2);
                    int mm = wm + mi * 16 + gid + ((r & 1) << 3);
                    split_tf32(Asrc[kk * STR + mm], ah[mi][r], al[mi][r]);
                }
#pragma unroll
            for (int h = 0; h < 2; ++h) {
                uint32_t bh[4][2], bl[4][2];
#pragma unroll
                for (int ni = 0; ni < 4; ++ni) {
                    int nn = wn + (h * 4 + ni) * 8 + gid;
                    uint2 p0 = Ws_p[(ks + tig) * STR + nn];
                    uint2 p1 = Ws_p[(ks + tig + 4) * STR + nn];
                    bh[ni][0] = p0.x; bl[ni][0] = p0.y;
                    bh[ni][1] = p1.x; bl[ni][1] = p1.y;
                }
#pragma unroll
                for (int mi = 0; mi < 2; ++mi)
#pragma unroll
                    for (int ni = 0; ni < 4; ++ni) {
                        float* c = acc[mi][h * 4 + ni];
                        mma8(c, ah[mi], bh[ni]);
                        mma8(c, ah[mi], bl[ni]);
                        mma8(c, al[mi], bh[ni]);
                    }
            }
        }
        __syncthreads();
    }

    // epilogue 2
    {
        float bb0[8], bb1[8];
#pragma unroll
        for (int ni = 0; ni < 8; ++ni) {
            int n0 = wn + ni * 8 + tig * 2;
            bb0[ni] = b2[n0];
            bb1[ni] = b2[n0 + 1];
        }
        if (EDGE) {
            float* mout = g_msg + ((size_t)b * NEDGES + m0) * DIM;
#pragma unroll
            for (int mi = 0; mi < 2; ++mi) {
                int mA = wm + mi * 16 + gid, mB = mA + 8;
#pragma unroll
                for (int ni = 0; ni < 8; ++ni) {
                    int n0 = wn + ni * 8 + tig * 2;
                    float2 vA = make_float2(lrelu(acc[mi][ni][0] + bb0[ni]),
                                            lrelu(acc[mi][ni][1] + bb1[ni]));
                    float2 vB = make_float2(lrelu(acc[mi][ni][2] + bb0[ni]),
                                            lrelu(acc[mi][ni][3] + bb1[ni]));
                    *(float2*)(mout + (size_t)mA * DIM + n0) = vA;
                    *(float2*)(mout + (size_t)mB * DIM + n0) = vB;
                }
            }
        } else {
            float* hout = g_h + (size_t)b * NNODES * DIM;
#pragma unroll
            for (int mi = 0; mi < 2; ++mi) {
                int mA = wm + mi * 16 + gid, mB = mA + 8;
                int nA = m0 + mA, nB = m0 + mB;
#pragma unroll
                for (int ni = 0; ni < 8; ++ni) {
                    int n0 = wn + ni * 8 + tig * 2;
                    if (nA < NNODES) {
                        float2* p = (float2*)(hout + (size_t)nA * DIM + n0);
                        float2 o = *p;
                        o.x += lrelu(acc[mi][ni][0] + bb0[ni]);
                        o.y += lrelu(acc[mi][ni][1] + bb1[ni]);
                        *p = o;
                    }
                    if (nB < NNODES) {
                        float2* p = (float2*)(hout + (size_t)nB * DIM + n0);
                        float2 o = *p;
                        o.x += lrelu(acc[mi][ni][2] + bb0[ni]);
                        o.y += lrelu(acc[mi][ni][3] + bb1[ni]);
                        *p = o;
                    }
                }
            }
        }
    }
}

// -------------------- CSR gather-mean aggregation ---------------------------
__global__ void k_aggr() {
    int b = blockIdx.y;
    int n = blockIdx.x * 2 + (threadIdx.x >> 7);
    int j = threadIdx.x & 127;
    const float* mb = g_msg + (size_t)b * NEDGES * DIM;
    int s = g_off[n], t = g_off[n + 1];
    float sum = 0.f;
    for (int i = s; i < t; ++i)
        sum += mb[(size_t)g_perm[i] * DIM + j];
    g_aggr[((size_t)b * NNODES + n) * DIM + j] = sum * g_recip[n];
}

// ----------------------- coord update (tanh GEMV) ---------------------------
__global__ void k_coord(const float* __restrict__ cw, const float* __restrict__ cb) {
    int b    = blockIdx.y;
    int wid  = threadIdx.x >> 5;
    int lane = threadIdx.x & 31;
    int n    = blockIdx.x * 8 + wid;
    if (n >= NNODES) return;
    const float* ar = g_aggr + ((size_t)b * NNODES + n) * DIM;
    float4 a = *(const float4*)(ar + lane * 4);
    float4 w = *(const float4*)(cw + lane * 4);
    float s = a.x * w.x + a.y * w.y + a.z * w.z + a.w * w.w;
#pragma unroll
    for (int o = 16; o; o >>= 1) s += __shfl_xor_sync(0xffffffffu, s, o);
    if (lane == 0) {
        float t = tanhf(s + cb[0]) * 0.1f;
        float* p = &g_pos[((size_t)b * NNODES + n) * 3];
        p[0] += t; p[1] += t; p[2] += t;
    }
}

// ----------------------- mean + projection ----------------------------------
__global__ void k_meanpart() {
    int b = blockIdx.y, p = blockIdx.x, j = threadIdx.x;
    const float* hb = g_h + (size_t)b * NNODES * DIM;
    const int span = NNODES / NPART;
    float s = 0.f;
    int n0 = p * span;
    for (int n = n0; n < n0 + span; ++n) s += hb[(size_t)n * DIM + j];
    g_hpart[(b * NPART + p) * DIM + j] = s;
}
__global__ void k_proj(const float* __restrict__ wp, const float* __restrict__ bp,
                       float* __restrict__ out) {
    __shared__ float hm[BATCH * DIM];
    int tid = threadIdx.x;
    {
        int b = tid >> 7, j = tid & 127;
        float s = 0.f;
        for (int p = 0; p < NPART; ++p) s += g_hpart[(b * NPART + p) * DIM + j];
        hm[b * DIM + j] = s * (1.0f / NNODES);
    }
    __syncthreads();
    if (tid < BATCH * OUTD) {
        int b = tid / OUTD, o = tid % OUTD;
        float s = bp[o];
        for (int j = 0; j < DIM; ++j) s = fmaf(hm[b * DIM + j], wp[j * OUTD + o], s);
        out[b * OUTD + o] = lrelu(s);
    }
}

// ---------------------------------------------------------------------------
extern "C" void kernel_launch(void* const* d_in, const int* in_sizes, int n_in,
                              void* d_out, int out_size) {
    const float* x   = (const float*)d_in[0];
    const int*   ei  = (const int*)  d_in[1];
    const float* w0  = (const float*)d_in[2];
    const float* b0  = (const float*)d_in[3];
    const float* ew1 = (const float*)d_in[4];
    const float* eb1 = (const float*)d_in[5];
    const float* ew2 = (const float*)d_in[6];
    const float* eb2 = (const float*)d_in[7];
    const float* cw  = (const float*)d_in[8];
    const float* cb  = (const float*)d_in[9];
    const float* nw1 = (const float*)d_in[10];
    const float* nb1 = (const float*)d_in[11];
    const float* nw2 = (const float*)d_in[12];
    const float* nb2 = (const float*)d_in[13];
    const float* wp  = (const float*)d_in[14];
    const float* bp  = (const float*)d_in[15];
    float* out = (float*)d_out;

    const int* row = ei;
    const int* col = ei + NEDGES;

    const int SMEM_MLP =
        BK * STR * 4            // As (fp32)
        + BK * STR * 8          // Ws_p (uint2)
        + TN * STR * 4          // Hs
        + TM * 4                // dsq
        + 2 * TM * 4;           // nid   => 119,808 bytes

    cudaFuncSetAttribute(mlp_kernel<true>,
                         cudaFuncAttributeMaxDynamicSharedMemorySize, SMEM_MLP);
    cudaFuncSetAttribute(mlp_kernel<false>,
                         cudaFuncAttributeMaxDynamicSharedMemorySize, SMEM_MLP);

    // CSR build (deterministic after per-node sort)
    k_zero_cnt<<<(NNODES + 255) / 256, 256>>>();
    k_count<<<(NEDGES + 255) / 256, 256>>>(col);
    k_scan<<<1, 1024>>>();
    k_fill<<<(NEDGES + 255) / 256, 256>>>(col);
    k_sort<<<(NNODES + 127) / 128, 128>>>();

    // init + weight prep (once per launch)
    k_init_pos<<<(BATCH * NNODES * 3 + 255) / 256, 256>>>(x);
    k_h0<<<(BATCH * NNODES * DIM + 255) / 256, 256>>>(w0, b0);
    k_wprep<<<96, 256>>>(ew1, ew2, nw1, nw2);

    for (int l = 0; l < NLAYERS; ++l) {
        mlp_kernel<true><<<dim3(NEDGES / TM, BATCH), NTHREADS, SMEM_MLP>>>(
            row, col, l * 24 + 0, l * 24 + 8,
            eb1 + l * DIM, eb2 + l * DIM,
            ew1 + (size_t)l * 257 * DIM + 256 * DIM);
        k_aggr<<<dim3(NNODES / 2, BATCH), 256>>>();
        k_coord<<<dim3(NNODES / 8, BATCH), 256>>>(cw + l * DIM, cb + l);
        mlp_kernel<false><<<dim3((NNODES + TM - 1) / TM, BATCH), NTHREADS, SMEM_MLP>>>(
            row, col, l * 24 + 12, l * 24 + 20,
            nb1 + l * DIM, nb2 + l * DIM, nullptr);
    }

    k_meanpart<<<dim3(NPART, BATCH), 128>>>();
    k_proj<<<1, 512>>>(wp, bp, out);
}

// round 11
// speedup vs baseline: 2.0575x; 1.9075x over previous
#include <cuda_runtime.h>
#include <math.h>
#include <stdint.h>

// ---------------------------------------------------------------------------
// EGNN  B=4, N=10000, E=160000, D=128, OUT=64, L=4
// R10: GEMMs on mma.sync m16n8k16 BF16, 3xBF16 split (hi*hi+hi*lo+lo*hi,
//      fp32 accum) -> half the tensor instructions of the tf32 path (R5).
//      k2-major packed-bf16x2 SMEM tiles, stride 136 (conflict-free frags).
//      Weights pre-split once; hidden written pre-split by epilogue 1.
// ---------------------------------------------------------------------------
#define BATCH    4
#define NNODES   10000
#define NEDGES   160000
#define DIM      128
#define OUTD     64
#define NLAYERS  4
#define NEG      0.01f

#define TM       128
#define TN       128
#define BK       32
#define S2       136        // u32 stride per k2-row (136 % 32 == 8)
#define NTHREADS 256
#define NPART    20

// SMEM layout in u32 units
#define AH_OFF   0                  // 16*136
#define AL_OFF   2176
#define WH_OFF   4352
#define WL_OFF   6528
#define HH_OFF   8704               // 64*136
#define HL_OFF   17408
#define DSQ_OFF  26112              // 128 floats
#define NID_OFF  26240              // 256 ints
#define SMEM_U32 26496              // 105,984 bytes

// ------------------------- device scratch (no mallocs) ---------------------
__device__ float g_pos[BATCH * NNODES * 3];
__device__ float g_h[(size_t)BATCH * NNODES * DIM];
__device__ float g_aggr[(size_t)BATCH * NNODES * DIM];
__device__ float g_msg[(size_t)BATCH * NEDGES * DIM];
__device__ int   g_cnt[NNODES];
__device__ float g_recip[NNODES];
__device__ int   g_off[NNODES + 1];
__device__ int   g_cursor[NNODES];
__device__ int   g_perm[NEDGES];
__device__ float g_hpart[BATCH * NPART * DIM];
// pre-split packed weights: 96 chunk-slots x (2176 hi + 2176 lo) u32
__device__ uint32_t g_wt[96 * 4352];

__device__ __forceinline__ float lrelu(float x) { return x > 0.f ? x : NEG * x; }

// ---- bf16x2 split-pack: (e,o) -> hi pack (e low half), lo pack ------------
__device__ __forceinline__ void split_pack(float e, float o,
                                           uint32_t& hi, uint32_t& lo) {
    asm("cvt.rn.bf16x2.f32 %0, %1, %2;" : "=r"(hi) : "f"(o), "f"(e));
    float eh = __uint_as_float(hi << 16);
    float oh = __uint_as_float(hi & 0xffff0000u);
    asm("cvt.rn.bf16x2.f32 %0, %1, %2;" : "=r"(lo) : "f"(o - oh), "f"(e - eh));
}

__device__ __forceinline__ void mmabf(float* c, const uint32_t* a,
                                      const uint32_t* b) {
    asm("mma.sync.aligned.m16n8k16.row.col.f32.bf16.bf16.f32 "
        "{%0,%1,%2,%3}, {%4,%5,%6,%7}, {%8,%9}, {%0,%1,%2,%3};"
        : "+f"(c[0]), "+f"(c[1]), "+f"(c[2]), "+f"(c[3])
        : "r"(a[0]), "r"(a[1]), "r"(a[2]), "r"(a[3]), "r"(b[0]), "r"(b[1]));
}

// ------------------------------ CSR build ----------------------------------
__global__ void k_zero_cnt() {
    int n = blockIdx.x * blockDim.x + threadIdx.x;
    if (n < NNODES) g_cnt[n] = 0;
}
__global__ void k_count(const int* __restrict__ col) {
    int e = blockIdx.x * blockDim.x + threadIdx.x;
    if (e < NEDGES) atomicAdd(&g_cnt[col[e]], 1);
}
__global__ void k_scan() {
    __shared__ int ss[1024];
    int tid = threadIdx.x;
    int running = 0;
    for (int c = 0; c < 10; ++c) {
        int n = c * 1024 + tid;
        int v = (n < NNODES) ? g_cnt[n] : 0;
        ss[tid] = v;
        __syncthreads();
        for (int d = 1; d < 1024; d <<= 1) {
            int t = (tid >= d) ? ss[tid - d] : 0;
            __syncthreads();
            ss[tid] += t;
            __syncthreads();
        }
        int incl = ss[tid];
        if (n < NNODES) {
            g_off[n + 1] = running + incl;
            g_cursor[n]  = running + incl - v;
            g_recip[n]   = 1.0f / fmaxf((float)v, 1.0f);
        }
        if (c == 0 && tid == 0) g_off[0] = 0;
        int tot = ss[1023];
        __syncthreads();
        running += tot;
    }
}
__global__ void k_fill(const int* __restrict__ col) {
    int e = blockIdx.x * blockDim.x + threadIdx.x;
    if (e < NEDGES) {
        int p = atomicAdd(&g_cursor[col[e]], 1);
        g_perm[p] = e;
    }
}
__global__ void k_sort() {
    int n = blockIdx.x * blockDim.x + threadIdx.x;
    if (n >= NNODES) return;
    int s = g_off[n], t = g_off[n + 1];
    for (int i = s + 1; i < t; ++i) {
        int v = g_perm[i];
        int j = i - 1;
        while (j >= s && g_perm[j] > v) { g_perm[j + 1] = g_perm[j]; --j; }
        g_perm[j + 1] = v;
    }
}

// ------------------------------ init ---------------------------------------
__global__ void k_init_pos(const float* __restrict__ x) {
    int i = blockIdx.x * blockDim.x + threadIdx.x;
    if (i < BATCH * NNODES * 3) g_pos[i] = x[i];
}
__global__ void k_h0(const float* __restrict__ w0, const float* __restrict__ b0) {
    int i = blockIdx.x * blockDim.x + threadIdx.x;
    if (i >= BATCH * NNODES * DIM) return;
    int j  = i & (DIM - 1);
    int bn = i >> 7;
    const float* p = &g_pos[bn * 3];
    float v = b0[j] + p[0] * w0[j] + p[1] * w0[DIM + j] + p[2] * w0[2 * DIM + j];
    g_h[i] = lrelu(v);
}

// -------- weight prep: bf16-split + pack k-pairs, tile layout = SMEM --------
// slot = l*24 + c24.  c24: 0-7 ew1 (K=256), 8-11 ew2, 12-19 nw1, 20-23 nw2.
__global__ void k_wprep(const float* __restrict__ ew1, const float* __restrict__ ew2,
                        const float* __restrict__ nw1, const float* __restrict__ nw2) {
    int slot = blockIdx.x;
    int l = slot / 24, c24 = slot % 24;
    const float* W; int k0;
    if (c24 < 8)       { W = ew1 + (size_t)l * 257 * DIM; k0 = c24 * 32; }
    else if (c24 < 12) { W = ew2 + (size_t)l * DIM * DIM; k0 = (c24 - 8) * 32; }
    else if (c24 < 20) { W = nw1 + (size_t)l * 2 * DIM * DIM; k0 = (c24 - 12) * 32; }
    else               { W = nw2 + (size_t)l * DIM * DIM; k0 = (c24 - 20) * 32; }
    uint32_t* dh = g_wt + (size_t)slot * 4352;
    uint32_t* dl = dh + 2176;
    for (int i = threadIdx.x; i < 2176; i += 256) {
        int k2 = i / S2, n = i - k2 * S2;
        uint32_t hi = 0, lo = 0;
        if (n < 128)
            split_pack(W[(size_t)(k0 + 2 * k2) * DIM + n],
                       W[(size_t)(k0 + 2 * k2 + 1) * DIM + n], hi, lo);
        dh[i] = hi;
        dl[i] = lo;
    }
}

// --------------------- fused 2-layer MLP GEMM kernel ------------------------
// CTA 128x128, 8 warps, warp tile 32x64. bf16 m16n8k16, 3-pass split.
template <bool EDGE>
__global__ void __launch_bounds__(NTHREADS)
mlp_kernel(const int* __restrict__ row, const int* __restrict__ col,
           int slot1, int slot2,
           const float* __restrict__ b1, const float* __restrict__ b2,
           const float* __restrict__ w1last)
{
    extern __shared__ uint32_t sm[];
    float* dsq = (float*)(sm + DSQ_OFF);
    int*   nid = (int*)(sm + NID_OFF);

    const int b    = blockIdx.y;
    const int m0   = blockIdx.x * TM;
    const int tid  = threadIdx.x;
    const int wid  = tid >> 5;
    const int lane = tid & 31;
    const int gid  = lane >> 2;   // 0..7
    const int tig  = lane & 3;    // 0..3
    const int wm   = (wid & 3) * 32;    // 4 warps over M=128
    const int wn   = (wid >> 2) * 64;   // 2 warps over N=128

    const float* hb = g_h    + (size_t)b * NNODES * DIM;
    const float* ab = g_aggr + (size_t)b * NNODES * DIM;

    if (EDGE) {
        for (int i = tid; i < TM; i += NTHREADS) {
            int e = m0 + i;
            int r = row[e], c = col[e];
            nid[i]      = r;
            nid[TM + i] = c;
            const float* pr = &g_pos[((size_t)b * NNODES + r) * 3];
            const float* pc = &g_pos[((size_t)b * NNODES + c) * 3];
            float dx = pr[0] - pc[0], dy = pr[1] - pc[1], dz = pr[2] - pc[2];
            dsq[i] = dx * dx + dy * dy + dz * dz;
        }
        __syncthreads();
    }

    float acc[2][8][4];
#pragma unroll
    for (int mi = 0; mi < 2; ++mi)
#pragma unroll
        for (int ni = 0; ni < 8; ++ni)
#pragma unroll
            for (int c = 0; c < 4; ++c) acc[mi][ni][c] = 0.f;

    // ---------------- GEMM 1: K = 256 (8 chunks of 32) ----------------------
#pragma unroll 1
    for (int kc = 0; kc < 8; ++kc) {
        const int k0 = kc * BK;
        // gathered A chunk -> split+pack -> k2-major SMEM
        for (int s = tid; s < TM * 8; s += NTHREADS) {
            int ei = s >> 3, q = s & 7;
            const float* src;
            if (EDGE) {
                int node = (kc < 4) ? nid[ei] : nid[TM + ei];
                int kh   = (kc < 4) ? k0 : (k0 - DIM);
                src = hb + (size_t)node * DIM + kh + q * 4;
            } else {
                int node = m0 + ei;
                if (node >= NNODES) node = NNODES - 1;
                src = (kc < 4) ? (hb + (size_t)node * DIM + k0 + q * 4)
                               : (ab + (size_t)node * DIM + (k0 - DIM) + q * 4);
            }
            float4 v = *(const float4*)src;
            uint32_t h0, l0, h1, l1;
            split_pack(v.x, v.y, h0, l0);
            split_pack(v.z, v.w, h1, l1);
            sm[AH_OFF + (2 * q)     * S2 + ei] = h0;
            sm[AL_OFF + (2 * q)     * S2 + ei] = l0;
            sm[AH_OFF + (2 * q + 1) * S2 + ei] = h1;
            sm[AL_OFF + (2 * q + 1) * S2 + ei] = l1;
        }
        // pre-split W1 chunk: raw uint4 copy (hi tile then lo tile)
        {
            const uint4* wsrc = (const uint4*)(g_wt + (size_t)(slot1 + kc) * 4352);
            uint4* wdst = (uint4*)(sm + WH_OFF);
            for (int s = tid; s < 1088; s += NTHREADS) wdst[s] = wsrc[s];
        }
        __syncthreads();
#pragma unroll
        for (int k8 = 0; k8 < 2; ++k8) {
            const int ks2 = k8 * 8;
            uint32_t ah[2][4], al[2][4];
#pragma unroll
            for (int mi = 0; mi < 2; ++mi) {
                int m = wm + mi * 16 + gid;
                ah[mi][0] = sm[AH_OFF + (ks2 + tig) * S2 + m];
                ah[mi][1] = sm[AH_OFF + (ks2 + tig) * S2 + m + 8];
                ah[mi][2] = sm[AH_OFF + (ks2 + tig + 4) * S2 + m];
                ah[mi][3] = sm[AH_OFF + (ks2 + tig + 4) * S2 + m + 8];
                al[mi][0] = sm[AL_OFF + (ks2 + tig) * S2 + m];
                al[mi][1] = sm[AL_OFF + (ks2 + tig) * S2 + m + 8];
                al[mi][2] = sm[AL_OFF + (ks2 + tig + 4) * S2 + m];
                al[mi][3] = sm[AL_OFF + (ks2 + tig + 4) * S2 + m + 8];
            }
#pragma unroll
            for (int ni = 0; ni < 8; ++ni) {
                int nn = wn + ni * 8 + gid;
                uint32_t bh[2], bl[2];
                bh[0] = sm[WH_OFF + (ks2 + tig) * S2 + nn];
                bh[1] = sm[WH_OFF + (ks2 + tig + 4) * S2 + nn];
                bl[0] = sm[WL_OFF + (ks2 + tig) * S2 + nn];
                bl[1] = sm[WL_OFF + (ks2 + tig + 4) * S2 + nn];
#pragma unroll
                for (int mi = 0; mi < 2; ++mi) {
                    float* c = acc[mi][ni];
                    mmabf(c, ah[mi], bh);
                    mmabf(c, ah[mi], bl);
                    mmabf(c, al[mi], bh);
                }
            }
        }
        __syncthreads();
    }

    // epilogue 1: + b1 (+ dsq*W1[256]), lrelu, write packed hidden (feat-major)
    {
        float bb0[8], bb1[8], wl0[8], wl1[8];
#pragma unroll
        for (int ni = 0; ni < 8; ++ni) {
            int n0 = wn + ni * 8 + tig * 2;
            bb0[ni] = b1[n0];
            bb1[ni] = b1[n0 + 1];
            if (EDGE) { wl0[ni] = w1last[n0]; wl1[ni] = w1last[n0 + 1]; }
        }
        float dA[2] = {0.f, 0.f}, dB[2] = {0.f, 0.f};
        if (EDGE) {
#pragma unroll
            for (int mi = 0; mi < 2; ++mi) {
                dA[mi] = dsq[wm + mi * 16 + gid];
                dB[mi] = dsq[wm + mi * 16 + gid + 8];
            }
        }
#pragma unroll
        for (int mi = 0; mi < 2; ++mi) {
            int mA = wm + mi * 16 + gid, mB = mA + 8;
#pragma unroll
            for (int ni = 0; ni < 8; ++ni) {
                int n0 = wn + ni * 8 + tig * 2;
                int k2 = n0 >> 1;
                float v0 = acc[mi][ni][0] + bb0[ni];
                float v1 = acc[mi][ni][1] + bb1[ni];
                float v2 = acc[mi][ni][2] + bb0[ni];
                float v3 = acc[mi][ni][3] + bb1[ni];
                if (EDGE) {
                    v0 = fmaf(dA[mi], wl0[ni], v0); v1 = fmaf(dA[mi], wl1[ni], v1);
                    v2 = fmaf(dB[mi], wl0[ni], v2); v3 = fmaf(dB[mi], wl1[ni], v3);
                }
                uint32_t h, l;
                split_pack(lrelu(v0), lrelu(v1), h, l);
                sm[HH_OFF + k2 * S2 + mA] = h;
                sm[HL_OFF + k2 * S2 + mA] = l;
                split_pack(lrelu(v2), lrelu(v3), h, l);
                sm[HH_OFF + k2 * S2 + mB] = h;
                sm[HL_OFF + k2 * S2 + mB] = l;
            }
        }
    }
    __syncthreads();

    // ---------------- GEMM 2: K = 128 (4 chunks of 32) ----------------------
#pragma unroll
    for (int mi = 0; mi < 2; ++mi)
#pragma unroll
        for (int ni = 0; ni < 8; ++ni)
#pragma unroll
            for (int c = 0; c < 4; ++c) acc[mi][ni][c] = 0.f;

#pragma unroll 1
    for (int kc = 0; kc < 4; ++kc) {
        {
            const uint4* wsrc = (const uint4*)(g_wt + (size_t)(slot2 + kc) * 4352);
            uint4* wdst = (uint4*)(sm + WH_OFF);
            for (int s = tid; s < 1088; s += NTHREADS) wdst[s] = wsrc[s];
        }
        __syncthreads();
#pragma unroll
        for (int k8 = 0; k8 < 2; ++k8) {
            const int ks2w = k8 * 8;
            const int ks2a = kc * 16 + k8 * 8;
            uint32_t ah[2][4], al[2][4];
#pragma unroll
            for (int mi = 0; mi < 2; ++mi) {
                int m = wm + mi * 16 + gid;
                ah[mi][0] = sm[HH_OFF + (ks2a + tig) * S2 + m];
                ah[mi][1] = sm[HH_OFF + (ks2a + tig) * S2 + m + 8];
                ah[mi][2] = sm[HH_OFF + (ks2a + tig + 4) * S2 + m];
                ah[mi][3] = sm[HH_OFF + (ks2a + tig + 4) * S2 + m + 8];
                al[mi][0] = sm[HL_OFF + (ks2a + tig) * S2 + m];
                al[mi][1] = sm[HL_OFF + (ks2a + tig) * S2 + m + 8];
                al[mi][2] = sm[HL_OFF + (ks2a + tig + 4) * S2 + m];
                al[mi][3] = sm[HL_OFF + (ks2a + tig + 4) * S2 + m + 8];
            }
#pragma unroll
            for (int ni = 0; ni < 8; ++ni) {
                int nn = wn + ni * 8 + gid;
                uint32_t bh[2], bl[2];
                bh[0] = sm[WH_OFF + (ks2w + tig) * S2 + nn];
                bh[1] = sm[WH_OFF + (ks2w + tig + 4) * S2 + nn];
                bl[0] = sm[WL_OFF + (ks2w + tig) * S2 + nn];
                bl[1] = sm[WL_OFF + (ks2w + tig + 4) * S2 + nn];
#pragma unroll
                for (int mi = 0; mi < 2; ++mi) {
                    float* c = acc[mi][ni];
                    mmabf(c, ah[mi], bh);
                    mmabf(c, ah[mi], bl);
                    mmabf(c, al[mi], bh);
                }
            }
        }
        __syncthreads();
    }

    // epilogue 2
    {
        float bb0[8], bb1[8];
#pragma unroll
        for (int ni = 0; ni < 8; ++ni) {
            int n0 = wn + ni * 8 + tig * 2;
            bb0[ni] = b2[n0];
            bb1[ni] = b2[n0 + 1];
        }
        if (EDGE) {
            float* mout = g_msg + ((size_t)b * NEDGES + m0) * DIM;
#pragma unroll
            for (int mi = 0; mi < 2; ++mi) {
                int mA = wm + mi * 16 + gid, mB = mA + 8;
#pragma unroll
                for (int ni = 0; ni < 8; ++ni) {
                    int n0 = wn + ni * 8 + tig * 2;
                    float2 vA = make_float2(lrelu(acc[mi][ni][0] + bb0[ni]),
                                            lrelu(acc[mi][ni][1] + bb1[ni]));
                    float2 vB = make_float2(lrelu(acc[mi][ni][2] + bb0[ni]),
                                            lrelu(acc[mi][ni][3] + bb1[ni]));
                    *(float2*)(mout + (size_t)mA * DIM + n0) = vA;
                    *(float2*)(mout + (size_t)mB * DIM + n0) = vB;
                }
            }
        } else {
            float* hout = g_h + (size_t)b * NNODES * DIM;
#pragma unroll
            for (int mi = 0; mi < 2; ++mi) {
                int mA = wm + mi * 16 + gid, mB = mA + 8;
                int nA = m0 + mA, nB = m0 + mB;
#pragma unroll
                for (int ni = 0; ni < 8; ++ni) {
                    int n0 = wn + ni * 8 + tig * 2;
                    if (nA < NNODES) {
                        float2* p = (float2*)(hout + (size_t)nA * DIM + n0);
                        float2 o = *p;
                        o.x += lrelu(acc[mi][ni][0] + bb0[ni]);
                        o.y += lrelu(acc[mi][ni][1] + bb1[ni]);
                        *p = o;
                    }
                    if (nB < NNODES) {
                        float2* p = (float2*)(hout + (size_t)nB * DIM + n0);
                        float2 o = *p;
                        o.x += lrelu(acc[mi][ni][2] + bb0[ni]);
                        o.y += lrelu(acc[mi][ni][3] + bb1[ni]);
                        *p = o;
                    }
                }
            }
        }
    }
}

// -------------------- CSR gather-mean aggregation ---------------------------
__global__ void k_aggr() {
    int b = blockIdx.y;
    int n = blockIdx.x * 2 + (threadIdx.x >> 7);
    int j = threadIdx.x & 127;
    const float* mb = g_msg + (size_t)b * NEDGES * DIM;
    int s = g_off[n], t = g_off[n + 1];
    float sum = 0.f;
    for (int i = s; i < t; ++i)
        sum += mb[(size_t)g_perm[i] * DIM + j];
    g_aggr[((size_t)b * NNODES + n) * DIM + j] = sum * g_recip[n];
}

// ----------------------- coord update (tanh GEMV) ---------------------------
__global__ void k_coord(const float* __restrict__ cw, const float* __restrict__ cb) {
    int b    = blockIdx.y;
    int wid  = threadIdx.x >> 5;
    int lane = threadIdx.x & 31;
    int n    = blockIdx.x * 8 + wid;
    if (n >= NNODES) return;
    const float* ar = g_aggr + ((size_t)b * NNODES + n) * DIM;
    float4 a = *(const float4*)(ar + lane * 4);
    float4 w = *(const float4*)(cw + lane * 4);
    float s = a.x * w.x + a.y * w.y + a.z * w.z + a.w * w.w;
#pragma unroll
    for (int o = 16; o; o >>= 1) s += __shfl_xor_sync(0xffffffffu, s, o);
    if (lane == 0) {
        float t = tanhf(s + cb[0]) * 0.1f;
        float* p = &g_pos[((size_t)b * NNODES + n) * 3];
        p[0] += t; p[1] += t; p[2] += t;
    }
}

// ----------------------- mean + projection ----------------------------------
__global__ void k_meanpart() {
    int b = blockIdx.y, p = blockIdx.x, j = threadIdx.x;
    const float* hb = g_h + (size_t)b * NNODES * DIM;
    const int span = NNODES / NPART;
    float s = 0.f;
    int n0 = p * span;
    for (int n = n0; n < n0 + span; ++n) s += hb[(size_t)n * DIM + j];
    g_hpart[(b * NPART + p) * DIM + j] = s;
}
__global__ void k_proj(const float* __restrict__ wp, const float* __restrict__ bp,
                       float* __restrict__ out) {
    __shared__ float hm[BATCH * DIM];
    int tid = threadIdx.x;
    {
        int b = tid >> 7, j = tid & 127;
        float s = 0.f;
        for (int p = 0; p < NPART; ++p) s += g_hpart[(b * NPART + p) * DIM + j];
        hm[b * DIM + j] = s * (1.0f / NNODES);
    }
    __syncthreads();
    if (tid < BATCH * OUTD) {
        int b = tid / OUTD, o = tid % OUTD;
        float s = bp[o];
        for (int j = 0; j < DIM; ++j) s = fmaf(hm[b * DIM + j], wp[j * OUTD + o], s);
        out[b * OUTD + o] = lrelu(s);
    }
}

// ---------------------------------------------------------------------------
extern "C" void kernel_launch(void* const* d_in, const int* in_sizes, int n_in,
                              void* d_out, int out_size) {
    const float* x   = (const float*)d_in[0];
    const int*   ei  = (const int*)  d_in[1];
    const float* w0  = (const float*)d_in[2];
    const float* b0  = (const float*)d_in[3];
    const float* ew1 = (const float*)d_in[4];
    const float* eb1 = (const float*)d_in[5];
    const float* ew2 = (const float*)d_in[6];
    const float* eb2 = (const float*)d_in[7];
    const float* cw  = (const float*)d_in[8];
    const float* cb  = (const float*)d_in[9];
    const float* nw1 = (const float*)d_in[10];
    const float* nb1 = (const float*)d_in[11];
    const float* nw2 = (const float*)d_in[12];
    const float* nb2 = (const float*)d_in[13];
    const float* wp  = (const float*)d_in[14];
    const float* bp  = (const float*)d_in[15];
    float* out = (float*)d_out;

    const int* row = ei;
    const int* col = ei + NEDGES;

    const int SMEM_MLP = SMEM_U32 * 4;   // 105,984 bytes

    cudaFuncSetAttribute(mlp_kernel<true>,
                         cudaFuncAttributeMaxDynamicSharedMemorySize, SMEM_MLP);
    cudaFuncSetAttribute(mlp_kernel<false>,
                         cudaFuncAttributeMaxDynamicSharedMemorySize, SMEM_MLP);

    // CSR build (deterministic after per-node sort)
    k_zero_cnt<<<(NNODES + 255) / 256, 256>>>();
    k_count<<<(NEDGES + 255) / 256, 256>>>(col);
    k_scan<<<1, 1024>>>();
    k_fill<<<(NEDGES + 255) / 256, 256>>>(col);
    k_sort<<<(NNODES + 127) / 128, 128>>>();

    // init + weight prep (once per launch)
    k_init_pos<<<(BATCH * NNODES * 3 + 255) / 256, 256>>>(x);
    k_h0<<<(BATCH * NNODES * DIM + 255) / 256, 256>>>(w0, b0);
    k_wprep<<<96, 256>>>(ew1, ew2, nw1, nw2);

    for (int l = 0; l < NLAYERS; ++l) {
        mlp_kernel<true><<<dim3(NEDGES / TM, BATCH), NTHREADS, SMEM_MLP>>>(
            row, col, l * 24 + 0, l * 24 + 8,
            eb1 + l * DIM, eb2 + l * DIM,
            ew1 + (size_t)l * 257 * DIM + 256 * DIM);
        k_aggr<<<dim3(NNODES / 2, BATCH), 256>>>();
        k_coord<<<dim3(NNODES / 8, BATCH), 256>>>(cw + l * DIM, cb + l);
        mlp_kernel<false><<<dim3((NNODES + TM - 1) / TM, BATCH), NTHREADS, SMEM_MLP>>>(
            row, col, l * 24 + 12, l * 24 + 20,
            nb1 + l * DIM, nb2 + l * DIM, nullptr);
    }

    k_meanpart<<<dim3(NPART, BATCH), 128>>>();
    k_proj<<<1, 512>>>(wp, bp, out);
}

// round 12
// speedup vs baseline: 2.4089x; 1.1708x over previous
#include <cuda_runtime.h>
#include <math.h>
#include <stdint.h>

// ---------------------------------------------------------------------------
// EGNN  B=4, N=10000, E=160000, D=128, OUT=64, L=4
// R11: R10 (bf16 m16n8k16 3-pass, 3702us) + 2 CTAs/SM occupancy
//      (__launch_bounds__(256,2)); SMEM 106KB fits 2/SM -> cross-CTA overlap
//      of gather-latency and MMA phases. A-gather LDGs batched (unroll 4).
// ---------------------------------------------------------------------------
#define BATCH    4
#define NNODES   10000
#define NEDGES   160000
#define DIM      128
#define OUTD     64
#define NLAYERS  4
#define NEG      0.01f

#define TM       128
#define TN       128
#define BK       32
#define S2       136        // u32 stride per k2-row (136 % 32 == 8)
#define NTHREADS 256
#define NPART    20

// SMEM layout in u32 units
#define AH_OFF   0                  // 16*136
#define AL_OFF   2176
#define WH_OFF   4352
#define WL_OFF   6528
#define HH_OFF   8704               // 64*136
#define HL_OFF   17408
#define DSQ_OFF  26112              // 128 floats
#define NID_OFF  26240              // 256 ints
#define SMEM_U32 26496              // 105,984 bytes

// ------------------------- device scratch (no mallocs) ---------------------
__device__ float g_pos[BATCH * NNODES * 3];
__device__ float g_h[(size_t)BATCH * NNODES * DIM];
__device__ float g_aggr[(size_t)BATCH * NNODES * DIM];
__device__ float g_msg[(size_t)BATCH * NEDGES * DIM];
__device__ int   g_cnt[NNODES];
__device__ float g_recip[NNODES];
__device__ int   g_off[NNODES + 1];
__device__ int   g_cursor[NNODES];
__device__ int   g_perm[NEDGES];
__device__ float g_hpart[BATCH * NPART * DIM];
// pre-split packed weights: 96 chunk-slots x (2176 hi + 2176 lo) u32
__device__ uint32_t g_wt[96 * 4352];

__device__ __forceinline__ float lrelu(float x) { return x > 0.f ? x : NEG * x; }

// ---- bf16x2 split-pack: (e,o) -> hi pack (e low half), lo pack ------------
__device__ __forceinline__ void split_pack(float e, float o,
                                           uint32_t& hi, uint32_t& lo) {
    asm("cvt.rn.bf16x2.f32 %0, %1, %2;" : "=r"(hi) : "f"(o), "f"(e));
    float eh = __uint_as_float(hi << 16);
    float oh = __uint_as_float(hi & 0xffff0000u);
    asm("cvt.rn.bf16x2.f32 %0, %1, %2;" : "=r"(lo) : "f"(o - oh), "f"(e - eh));
}

__device__ __forceinline__ void mmabf(float* c, const uint32_t* a,
                                      const uint32_t* b) {
    asm("mma.sync.aligned.m16n8k16.row.col.f32.bf16.bf16.f32 "
        "{%0,%1,%2,%3}, {%4,%5,%6,%7}, {%8,%9}, {%0,%1,%2,%3};"
        : "+f"(c[0]), "+f"(c[1]), "+f"(c[2]), "+f"(c[3])
        : "r"(a[0]), "r"(a[1]), "r"(a[2]), "r"(a[3]), "r"(b[0]), "r"(b[1]));
}

// ------------------------------ CSR build ----------------------------------
__global__ void k_zero_cnt() {
    int n = blockIdx.x * blockDim.x + threadIdx.x;
    if (n < NNODES) g_cnt[n] = 0;
}
__global__ void k_count(const int* __restrict__ col) {
    int e = blockIdx.x * blockDim.x + threadIdx.x;
    if (e < NEDGES) atomicAdd(&g_cnt[col[e]], 1);
}
__global__ void k_scan() {
    __shared__ int ss[1024];
    int tid = threadIdx.x;
    int running = 0;
    for (int c = 0; c < 10; ++c) {
        int n = c * 1024 + tid;
        int v = (n < NNODES) ? g_cnt[n] : 0;
        ss[tid] = v;
        __syncthreads();
        for (int d = 1; d < 1024; d <<= 1) {
            int t = (tid >= d) ? ss[tid - d] : 0;
            __syncthreads();
            ss[tid] += t;
            __syncthreads();
        }
        int incl = ss[tid];
        if (n < NNODES) {
            g_off[n + 1] = running + incl;
            g_cursor[n]  = running + incl - v;
            g_recip[n]   = 1.0f / fmaxf((float)v, 1.0f);
        }
        if (c == 0 && tid == 0) g_off[0] = 0;
        int tot = ss[1023];
        __syncthreads();
        running += tot;
    }
}
__global__ void k_fill(const int* __restrict__ col) {
    int e = blockIdx.x * blockDim.x + threadIdx.x;
    if (e < NEDGES) {
        int p = atomicAdd(&g_cursor[col[e]], 1);
        g_perm[p] = e;
    }
}
__global__ void k_sort() {
    int n = blockIdx.x * blockDim.x + threadIdx.x;
    if (n >= NNODES) return;
    int s = g_off[n], t = g_off[n + 1];
    for (int i = s + 1; i < t; ++i) {
        int v = g_perm[i];
        int j = i - 1;
        while (j >= s && g_perm[j] > v) { g_perm[j + 1] = g_perm[j]; --j; }
        g_perm[j + 1] = v;
    }
}

// ------------------------------ init ---------------------------------------
__global__ void k_init_pos(const float* __restrict__ x) {
    int i = blockIdx.x * blockDim.x + threadIdx.x;
    if (i < BATCH * NNODES * 3) g_pos[i] = x[i];
}
__global__ void k_h0(const float* __restrict__ w0, const float* __restrict__ b0) {
    int i = blockIdx.x * blockDim.x + threadIdx.x;
    if (i >= BATCH * NNODES * DIM) return;
    int j  = i & (DIM - 1);
    int bn = i >> 7;
    const float* p = &g_pos[bn * 3];
    float v = b0[j] + p[0] * w0[j] + p[1] * w0[DIM + j] + p[2] * w0[2 * DIM + j];
    g_h[i] = lrelu(v);
}

// -------- weight prep: bf16-split + pack k-pairs, tile layout = SMEM --------
// slot = l*24 + c24.  c24: 0-7 ew1 (K=256), 8-11 ew2, 12-19 nw1, 20-23 nw2.
__global__ void k_wprep(const float* __restrict__ ew1, const float* __restrict__ ew2,
                        const float* __restrict__ nw1, const float* __restrict__ nw2) {
    int slot = blockIdx.x;
    int l = slot / 24, c24 = slot % 24;
    const float* W; int k0;
    if (c24 < 8)       { W = ew1 + (size_t)l * 257 * DIM; k0 = c24 * 32; }
    else if (c24 < 12) { W = ew2 + (size_t)l * DIM * DIM; k0 = (c24 - 8) * 32; }
    else if (c24 < 20) { W = nw1 + (size_t)l * 2 * DIM * DIM; k0 = (c24 - 12) * 32; }
    else               { W = nw2 + (size_t)l * DIM * DIM; k0 = (c24 - 20) * 32; }
    uint32_t* dh = g_wt + (size_t)slot * 4352;
    uint32_t* dl = dh + 2176;
    for (int i = threadIdx.x; i < 2176; i += 256) {
        int k2 = i / S2, n = i - k2 * S2;
        uint32_t hi = 0, lo = 0;
        if (n < 128)
            split_pack(W[(size_t)(k0 + 2 * k2) * DIM + n],
                       W[(size_t)(k0 + 2 * k2 + 1) * DIM + n], hi, lo);
        dh[i] = hi;
        dl[i] = lo;
    }
}

// --------------------- fused 2-layer MLP GEMM kernel ------------------------
// CTA 128x128, 8 warps, warp tile 32x64. bf16 m16n8k16, 3-pass split.
// 2 CTAs/SM: gather phase of one CTA overlaps MMA phase of the other.
template <bool EDGE>
__global__ void __launch_bounds__(NTHREADS, 2)
mlp_kernel(const int* __restrict__ row, const int* __restrict__ col,
           int slot1, int slot2,
           const float* __restrict__ b1, const float* __restrict__ b2,
           const float* __restrict__ w1last)
{
    extern __shared__ uint32_t sm[];
    float* dsq = (float*)(sm + DSQ_OFF);
    int*   nid = (int*)(sm + NID_OFF);

    const int b    = blockIdx.y;
    const int m0   = blockIdx.x * TM;
    const int tid  = threadIdx.x;
    const int wid  = tid >> 5;
    const int lane = tid & 31;
    const int gid  = lane >> 2;   // 0..7
    const int tig  = lane & 3;    // 0..3
    const int wm   = (wid & 3) * 32;    // 4 warps over M=128
    const int wn   = (wid >> 2) * 64;   // 2 warps over N=128

    const float* hb = g_h    + (size_t)b * NNODES * DIM;
    const float* ab = g_aggr + (size_t)b * NNODES * DIM;

    if (EDGE) {
        for (int i = tid; i < TM; i += NTHREADS) {
            int e = m0 + i;
            int r = row[e], c = col[e];
            nid[i]      = r;
            nid[TM + i] = c;
            const float* pr = &g_pos[((size_t)b * NNODES + r) * 3];
            const float* pc = &g_pos[((size_t)b * NNODES + c) * 3];
            float dx = pr[0] - pc[0], dy = pr[1] - pc[1], dz = pr[2] - pc[2];
            dsq[i] = dx * dx + dy * dy + dz * dz;
        }
        __syncthreads();
    }

    float acc[2][8][4];
#pragma unroll
    for (int mi = 0; mi < 2; ++mi)
#pragma unroll
        for (int ni = 0; ni < 8; ++ni)
#pragma unroll
            for (int c = 0; c < 4; ++c) acc[mi][ni][c] = 0.f;

    // ---------------- GEMM 1: K = 256 (8 chunks of 32) ----------------------
#pragma unroll 1
    for (int kc = 0; kc < 8; ++kc) {
        const int k0 = kc * BK;
        // gathered A chunk -> split+pack -> k2-major SMEM (4 batched LDG.128)
#pragma unroll 4
        for (int s = tid; s < TM * 8; s += NTHREADS) {
            int ei = s >> 3, q = s & 7;
            const float* src;
            if (EDGE) {
                int node = (kc < 4) ? nid[ei] : nid[TM + ei];
                int kh   = (kc < 4) ? k0 : (k0 - DIM);
                src = hb + (size_t)node * DIM + kh + q * 4;
            } else {
                int node = m0 + ei;
                if (node >= NNODES) node = NNODES - 1;
                src = (kc < 4) ? (hb + (size_t)node * DIM + k0 + q * 4)
                               : (ab + (size_t)node * DIM + (k0 - DIM) + q * 4);
            }
            float4 v = *(const float4*)src;
            uint32_t h0, l0, h1, l1;
            split_pack(v.x, v.y, h0, l0);
            split_pack(v.z, v.w, h1, l1);
            sm[AH_OFF + (2 * q)     * S2 + ei] = h0;
            sm[AL_OFF + (2 * q)     * S2 + ei] = l0;
            sm[AH_OFF + (2 * q + 1) * S2 + ei] = h1;
            sm[AL_OFF + (2 * q + 1) * S2 + ei] = l1;
        }
        // pre-split W1 chunk: raw uint4 copy (hi tile then lo tile)
        {
            const uint4* wsrc = (const uint4*)(g_wt + (size_t)(slot1 + kc) * 4352);
            uint4* wdst = (uint4*)(sm + WH_OFF);
#pragma unroll 4
            for (int s = tid; s < 1088; s += NTHREADS) wdst[s] = wsrc[s];
        }
        __syncthreads();
#pragma unroll
        for (int k8 = 0; k8 < 2; ++k8) {
            const int ks2 = k8 * 8;
            uint32_t ah[2][4], al[2][4];
#pragma unroll
            for (int mi = 0; mi < 2; ++mi) {
                int m = wm + mi * 16 + gid;
                ah[mi][0] = sm[AH_OFF + (ks2 + tig) * S2 + m];
                ah[mi][1] = sm[AH_OFF + (ks2 + tig) * S2 + m + 8];
                ah[mi][2] = sm[AH_OFF + (ks2 + tig + 4) * S2 + m];
                ah[mi][3] = sm[AH_OFF + (ks2 + tig + 4) * S2 + m + 8];
                al[mi][0] = sm[AL_OFF + (ks2 + tig) * S2 + m];
                al[mi][1] = sm[AL_OFF + (ks2 + tig) * S2 + m + 8];
                al[mi][2] = sm[AL_OFF + (ks2 + tig + 4) * S2 + m];
                al[mi][3] = sm[AL_OFF + (ks2 + tig + 4) * S2 + m + 8];
            }
#pragma unroll
            for (int ni = 0; ni < 8; ++ni) {
                int nn = wn + ni * 8 + gid;
                uint32_t bh[2], bl[2];
                bh[0] = sm[WH_OFF + (ks2 + tig) * S2 + nn];
                bh[1] = sm[WH_OFF + (ks2 + tig + 4) * S2 + nn];
                bl[0] = sm[WL_OFF + (ks2 + tig) * S2 + nn];
                bl[1] = sm[WL_OFF + (ks2 + tig + 4) * S2 + nn];
#pragma unroll
                for (int mi = 0; mi < 2; ++mi) {
                    float* c = acc[mi][ni];
                    mmabf(c, ah[mi], bh);
                    mmabf(c, ah[mi], bl);
                    mmabf(c, al[mi], bh);
                }
            }
        }
        __syncthreads();
    }

    // epilogue 1: + b1 (+ dsq*W1[256]), lrelu, write packed hidden (feat-major)
    {
        float bb0[8], bb1[8], wl0[8], wl1[8];
#pragma unroll
        for (int ni = 0; ni < 8; ++ni) {
            int n0 = wn + ni * 8 + tig * 2;
            bb0[ni] = b1[n0];
            bb1[ni] = b1[n0 + 1];
            if (EDGE) { wl0[ni] = w1last[n0]; wl1[ni] = w1last[n0 + 1]; }
        }
        float dA[2] = {0.f, 0.f}, dB[2] = {0.f, 0.f};
        if (EDGE) {
#pragma unroll
            for (int mi = 0; mi < 2; ++mi) {
                dA[mi] = dsq[wm + mi * 16 + gid];
                dB[mi] = dsq[wm + mi * 16 + gid + 8];
            }
        }
#pragma unroll
        for (int mi = 0; mi < 2; ++mi) {
            int mA = wm + mi * 16 + gid, mB = mA + 8;
#pragma unroll
            for (int ni = 0; ni < 8; ++ni) {
                int n0 = wn + ni * 8 + tig * 2;
                int k2 = n0 >> 1;
                float v0 = acc[mi][ni][0] + bb0[ni];
                float v1 = acc[mi][ni][1] + bb1[ni];
                float v2 = acc[mi][ni][2] + bb0[ni];
                float v3 = acc[mi][ni][3] + bb1[ni];
                if (EDGE) {
                    v0 = fmaf(dA[mi], wl0[ni], v0); v1 = fmaf(dA[mi], wl1[ni], v1);
                    v2 = fmaf(dB[mi], wl0[ni], v2); v3 = fmaf(dB[mi], wl1[ni], v3);
                }
                uint32_t h, l;
                split_pack(lrelu(v0), lrelu(v1), h, l);
                sm[HH_OFF + k2 * S2 + mA] = h;
                sm[HL_OFF + k2 * S2 + mA] = l;
                split_pack(lrelu(v2), lrelu(v3), h, l);
                sm[HH_OFF + k2 * S2 + mB] = h;
                sm[HL_OFF + k2 * S2 + mB] = l;
            }
        }
    }
    __syncthreads();

    // ---------------- GEMM 2: K = 128 (4 chunks of 32) ----------------------
#pragma unroll
    for (int mi = 0; mi < 2; ++mi)
#pragma unroll
        for (int ni = 0; ni < 8; ++ni)
#pragma unroll
            for (int c = 0; c < 4; ++c) acc[mi][ni][c] = 0.f;

#pragma unroll 1
    for (int kc = 0; kc < 4; ++kc) {
        {
            const uint4* wsrc = (const uint4*)(g_wt + (size_t)(slot2 + kc) * 4352);
            uint4* wdst = (uint4*)(sm + WH_OFF);
#pragma unroll 4
            for (int s = tid; s < 1088; s += NTHREADS) wdst[s] = wsrc[s];
        }
        __syncthreads();
#pragma unroll
        for (int k8 = 0; k8 < 2; ++k8) {
            const int ks2w = k8 * 8;
            const int ks2a = kc * 16 + k8 * 8;
            uint32_t ah[2][4], al[2][4];
#pragma unroll
            for (int mi = 0; mi < 2; ++mi) {
                int m = wm + mi * 16 + gid;
                ah[mi][0] = sm[HH_OFF + (ks2a + tig) * S2 + m];
                ah[mi][1] = sm[HH_OFF + (ks2a + tig) * S2 + m + 8];
                ah[mi][2] = sm[HH_OFF + (ks2a + tig + 4) * S2 + m];
                ah[mi][3] = sm[HH_OFF + (ks2a + tig + 4) * S2 + m + 8];
                al[mi][0] = sm[HL_OFF + (ks2a + tig) * S2 + m];
                al[mi][1] = sm[HL_OFF + (ks2a + tig) * S2 + m + 8];
                al[mi][2] = sm[HL_OFF + (ks2a + tig + 4) * S2 + m];
                al[mi][3] = sm[HL_OFF + (ks2a + tig + 4) * S2 + m + 8];
            }
#pragma unroll
            for (int ni = 0; ni < 8; ++ni) {
                int nn = wn + ni * 8 + gid;
                uint32_t bh[2], bl[2];
                bh[0] = sm[WH_OFF + (ks2w + tig) * S2 + nn];
                bh[1] = sm[WH_OFF + (ks2w + tig + 4) * S2 + nn];
                bl[0] = sm[WL_OFF + (ks2w + tig) * S2 + nn];
                bl[1] = sm[WL_OFF + (ks2w + tig + 4) * S2 + nn];
#pragma unroll
                for (int mi = 0; mi < 2; ++mi) {
                    float* c = acc[mi][ni];
                    mmabf(c, ah[mi], bh);
                    mmabf(c, ah[mi], bl);
                    mmabf(c, al[mi], bh);
                }
            }
        }
        __syncthreads();
    }

    // epilogue 2
    {
        float bb0[8], bb1[8];
#pragma unroll
        for (int ni = 0; ni < 8; ++ni) {
            int n0 = wn + ni * 8 + tig * 2;
            bb0[ni] = b2[n0];
            bb1[ni] = b2[n0 + 1];
        }
        if (EDGE) {
            float* mout = g_msg + ((size_t)b * NEDGES + m0) * DIM;
#pragma unroll
            for (int mi = 0; mi < 2; ++mi) {
                int mA = wm + mi * 16 + gid, mB = mA + 8;
#pragma unroll
                for (int ni = 0; ni < 8; ++ni) {
                    int n0 = wn + ni * 8 + tig * 2;
                    float2 vA = make_float2(lrelu(acc[mi][ni][0] + bb0[ni]),
                                            lrelu(acc[mi][ni][1] + bb1[ni]));
                    float2 vB = make_float2(lrelu(acc[mi][ni][2] + bb0[ni]),
                                            lrelu(acc[mi][ni][3] + bb1[ni]));
                    *(float2*)(mout + (size_t)mA * DIM + n0) = vA;
                    *(float2*)(mout + (size_t)mB * DIM + n0) = vB;
                }
            }
        } else {
            float* hout = g_h + (size_t)b * NNODES * DIM;
#pragma unroll
            for (int mi = 0; mi < 2; ++mi) {
                int mA = wm + mi * 16 + gid, mB = mA + 8;
                int nA = m0 + mA, nB = m0 + mB;
#pragma unroll
                for (int ni = 0; ni < 8; ++ni) {
                    int n0 = wn + ni * 8 + tig * 2;
                    if (nA < NNODES) {
                        float2* p = (float2*)(hout + (size_t)nA * DIM + n0);
                        float2 o = *p;
                        o.x += lrelu(acc[mi][ni][0] + bb0[ni]);
                        o.y += lrelu(acc[mi][ni][1] + bb1[ni]);
                        *p = o;
                    }
                    if (nB < NNODES) {
                        float2* p = (float2*)(hout + (size_t)nB * DIM + n0);
                        float2 o = *p;
                        o.x += lrelu(acc[mi][ni][2] + bb0[ni]);
                        o.y += lrelu(acc[mi][ni][3] + bb1[ni]);
                        *p = o;
                    }
                }
            }
        }
    }
}

// -------------------- CSR gather-mean aggregation ---------------------------
__global__ void k_aggr() {
    int b = blockIdx.y;
    int n = blockIdx.x * 2 + (threadIdx.x >> 7);
    int j = threadIdx.x & 127;
    const float* mb = g_msg + (size_t)b * NEDGES * DIM;
    int s = g_off[n], t = g_off[n + 1];
    float sum = 0.f;
    for (int i = s; i < t; ++i)
        sum += mb[(size_t)g_perm[i] * DIM + j];
    g_aggr[((size_t)b * NNODES + n) * DIM + j] = sum * g_recip[n];
}

// ----------------------- coord update (tanh GEMV) ---------------------------
__global__ void k_coord(const float* __restrict__ cw, const float* __restrict__ cb) {
    int b    = blockIdx.y;
    int wid  = threadIdx.x >> 5;
    int lane = threadIdx.x & 31;
    int n    = blockIdx.x * 8 + wid;
    if (n >= NNODES) return;
    const float* ar = g_aggr + ((size_t)b * NNODES + n) * DIM;
    float4 a = *(const float4*)(ar + lane * 4);
    float4 w = *(const float4*)(cw + lane * 4);
    float s = a.x * w.x + a.y * w.y + a.z * w.z + a.w * w.w;
#pragma unroll
    for (int o = 16; o; o >>= 1) s += __shfl_xor_sync(0xffffffffu, s, o);
    if (lane == 0) {
        float t = tanhf(s + cb[0]) * 0.1f;
        float* p = &g_pos[((size_t)b * NNODES + n) * 3];
        p[0] += t; p[1] += t; p[2] += t;
    }
}

// ----------------------- mean + projection ----------------------------------
__global__ void k_meanpart() {
    int b = blockIdx.y, p = blockIdx.x, j = threadIdx.x;
    const float* hb = g_h + (size_t)b * NNODES * DIM;
    const int span = NNODES / NPART;
    float s = 0.f;
    int n0 = p * span;
    for (int n = n0; n < n0 + span; ++n) s += hb[(size_t)n * DIM + j];
    g_hpart[(b * NPART + p) * DIM + j] = s;
}
__global__ void k_proj(const float* __restrict__ wp, const float* __restrict__ bp,
                       float* __restrict__ out) {
    __shared__ float hm[BATCH * DIM];
    int tid = threadIdx.x;
    {
        int b = tid >> 7, j = tid & 127;
        float s = 0.f;
        for (int p = 0; p < NPART; ++p) s += g_hpart[(b * NPART + p) * DIM + j];
        hm[b * DIM + j] = s * (1.0f / NNODES);
    }
    __syncthreads();
    if (tid < BATCH * OUTD) {
        int b = tid / OUTD, o = tid % OUTD;
        float s = bp[o];
        for (int j = 0; j < DIM; ++j) s = fmaf(hm[b * DIM + j], wp[j * OUTD + o], s);
        out[b * OUTD + o] = lrelu(s);
    }
}

// ---------------------------------------------------------------------------
extern "C" void kernel_launch(void* const* d_in, const int* in_sizes, int n_in,
                              void* d_out, int out_size) {
    const float* x   = (const float*)d_in[0];
    const int*   ei  = (const int*)  d_in[1];
    const float* w0  = (const float*)d_in[2];
    const float* b0  = (const float*)d_in[3];
    const float* ew1 = (const float*)d_in[4];
    const float* eb1 = (const float*)d_in[5];
    const float* ew2 = (const float*)d_in[6];
    const float* eb2 = (const float*)d_in[7];
    const float* cw  = (const float*)d_in[8];
    const float* cb  = (const float*)d_in[9];
    const float* nw1 = (const float*)d_in[10];
    const float* nb1 = (const float*)d_in[11];
    const float* nw2 = (const float*)d_in[12];
    const float* nb2 = (const float*)d_in[13];
    const float* wp  = (const float*)d_in[14];
    const float* bp  = (const float*)d_in[15];
    float* out = (float*)d_out;

    const int* row = ei;
    const int* col = ei + NEDGES;

    const int SMEM_MLP = SMEM_U32 * 4;   // 105,984 bytes -> 2 CTAs/SM

    cudaFuncSetAttribute(mlp_kernel<true>,
                         cudaFuncAttributeMaxDynamicSharedMemorySize, SMEM_MLP);
    cudaFuncSetAttribute(mlp_kernel<false>,
                         cudaFuncAttributeMaxDynamicSharedMemorySize, SMEM_MLP);

    // CSR build (deterministic after per-node sort)
    k_zero_cnt<<<(NNODES + 255) / 256, 256>>>();
    k_count<<<(NEDGES + 255) / 256, 256>>>(col);
    k_scan<<<1, 1024>>>();
    k_fill<<<(NEDGES + 255) / 256, 256>>>(col);
    k_sort<<<(NNODES + 127) / 128, 128>>>();

    // init + weight prep (once per launch)
    k_init_pos<<<(BATCH * NNODES * 3 + 255) / 256, 256>>>(x);
    k_h0<<<(BATCH * NNODES * DIM + 255) / 256, 256>>>(w0, b0);
    k_wprep<<<96, 256>>>(ew1, ew2, nw1, nw2);

    for (int l = 0; l < NLAYERS; ++l) {
        mlp_kernel<true><<<dim3(NEDGES / TM, BATCH), NTHREADS, SMEM_MLP>>>(
            row, col, l * 24 + 0, l * 24 + 8,
            eb1 + l * DIM, eb2 + l * DIM,
            ew1 + (size_t)l * 257 * DIM + 256 * DIM);
        k_aggr<<<dim3(NNODES / 2, BATCH), 256>>>();
        k_coord<<<dim3(NNODES / 8, BATCH), 256>>>(cw + l * DIM, cb + l);
        mlp_kernel<false><<<dim3((NNODES + TM - 1) / TM, BATCH), NTHREADS, SMEM_MLP>>>(
            row, col, l * 24 + 12, l * 24 + 20,
            nb1 + l * DIM, nb2 + l * DIM, nullptr);
    }

    k_meanpart<<<dim3(NPART, BATCH), 128>>>();
    k_proj<<<1, 512>>>(wp, bp, out);
}